// round 15
// baseline (speedup 1.0000x reference)
#include <cuda_runtime.h>

// FlowNet2 Resample2d (kernel_size=1) bilinear warp — FINAL (R6 optimum).
// input1: [B, C, H, W] float, input2 (flow): [B, 2, H, W] float
//
// Converged structure after 14 measured variants: 64x4 pixel tiles
// (256 threads, warps = 32-px half-rows, vertical neighbors co-resident),
// one thread per pixel, scalar gathers, channel loop unroll-4, 32 regs,
// 8 blocks/SM (~92% occupancy).
//
// Performance model (HW-calibrated): L1 sector-return bound at ~14 L1
// cycles per warp-channel = 4 scattered gathers x ~3.4 unique-sector
// wavefronts + 1 coalesced store wavefront. 124.6us ncu, ~4.15 TB/s HBM.
//
// Measured dead ends: LDG.64/LDG.128 gathers (wide scattered loads pay the
// sector bill once per 4B slice: 165/253us), smem staging (LDS conflicts +
// instr bloat: 395us), channel-lockstep barriers (174us), 32x8 & 64x2 tiles
// (lose vertical reuse / L1 density), __stcg stores, unroll-8 (occupancy),
// dual channel streams (issue pressure), paired sequential tiles (temporal
// locality loss: 143us), smem carveout (neutral), L1::evict_last (way
// contention: 130us). tex2Dgather barred (requires CUDA array = alloc).

#define BB 8
#define CC 32
#define HH 512
#define WW 512
#define HWSZ (HH * WW)   // 2^18

__global__ __launch_bounds__(256, 8)
void resample2d_kernel(const float* __restrict__ in1,
                       const float* __restrict__ flow,
                       float* __restrict__ out) {
    // Block tile: 64 px wide x 4 rows. Grid = 8 x-chunks * 128 y-chunks * 8 b.
    int blk = blockIdx.x;
    int x0 = (blk & 7) << 6;            // x-chunk * 64
    int y0 = ((blk >> 3) & 127) << 2;   // y-chunk * 4
    int b  = blk >> 10;                 // batch

    int w = x0 + (threadIdx.x & 63);
    int h = y0 + (threadIdx.x >> 6);
    int hw = (h << 9) | w;

    const float* fl = flow + ((size_t)b << 19); // b * 2 * HWSZ
    float dx = __ldg(fl + hw);
    float dy = __ldg(fl + HWSZ + hw);

    float xf = (float)w + dx;
    float yf = (float)h + dy;
    float x0f = floorf(xf);
    float y0f = floorf(yf);
    float alpha = xf - x0f;   // unclamped fractional weights
    float beta  = yf - y0f;

    int ix0 = (int)x0f;
    int iy0 = (int)y0f;
    int xL = min(max(ix0,     0), WW - 1);
    int xR = min(max(ix0 + 1, 0), WW - 1);
    int yT = min(max(iy0,     0), HH - 1);
    int yB = min(max(iy0 + 1, 0), HH - 1);

    float wTR = alpha * (1.0f - beta);
    float wBL = (1.0f - alpha) * beta;
    float wBR = alpha * beta;
    float wTL = 1.0f - wTR - wBL - wBR;

    const float* base = in1 + ((size_t)b << 23);   // b * C * HWSZ
    const float* pTL = base + ((yT << 9) + xL);
    const float* pTR = base + ((yT << 9) + xR);
    const float* pBL = base + ((yB << 9) + xL);
    const float* pBR = base + ((yB << 9) + xR);
    float* op = out + ((size_t)b << 23) + hw;

    #pragma unroll 4
    for (int c = 0; c < CC; c++) {
        int off = c << 18;   // c * HWSZ
        float v = wTL * __ldg(pTL + off)
                + wTR * __ldg(pTR + off)
                + wBL * __ldg(pBL + off)
                + wBR * __ldg(pBR + off);
        op[off] = v;
    }
}

extern "C" void kernel_launch(void* const* d_in, const int* in_sizes, int n_in,
                              void* d_out, int out_size) {
    const float* input1 = (const float*)d_in[0];
    const float* input2 = (const float*)d_in[1];
    float* out = (float*)d_out;

    const int blocks = 8 * 128 * BB;   // 8192 tiles of 64x4
    resample2d_kernel<<<blocks, 256>>>(input1, input2, out);
}

// round 16
// speedup vs baseline: 1.0199x; 1.0199x over previous
#include <cuda_runtime.h>

// FlowNet2 Resample2d (kernel_size=1) bilinear warp — FINAL (converged).
// input1: [B, C, H, W] float, input2 (flow): [B, 2, H, W] float
//
// Converged after 15 measured rounds: 64x4 pixel tiles (256 threads, warps
// = 32-px half-rows, vertically adjacent rows co-resident per SM), one
// thread per pixel, scalar gathers, channel loop unroll-4, 32 regs,
// 8 blocks/SM (~93% occupancy). 124.6-129us ncu (run noise +/-3us),
// ~4.1 TB/s HBM, L1 ~88% busy.
//
// Performance model (HW-calibrated): L1 sector-return bound at ~14 L1
// cycles per warp-channel = 4 scattered gathers x ~3.4 unique-sector
// wavefronts + 1 coalesced store wavefront. The sector bill is a
// warp-footprint invariant: lane permutation, px-per-thread, and load
// width cannot reduce it (wide scattered loads pay it per 4B slice).
//
// Measured dead ends: LDG.64/LDG.128 gathers (165/253us), smem staging
// (LDS conflicts + instr bloat, 395us), channel-lockstep barriers (174us),
// 32x8 / 64x2 tiles (lose vertical reuse or L1 density), __stcg, unroll-8
// (occupancy), dual channel streams (issue pressure), paired sequential
// tiles (temporal locality loss, 143us), smem carveout (neutral),
// L1::evict_last (way contention). tex2Dgather barred (requires CUDA
// array allocation). Identical-code rerun established the +/-3-4us noise
// band; all surviving variants are within it.

#define BB 8
#define CC 32
#define HH 512
#define WW 512
#define HWSZ (HH * WW)   // 2^18

__global__ __launch_bounds__(256, 8)
void resample2d_kernel(const float* __restrict__ in1,
                       const float* __restrict__ flow,
                       float* __restrict__ out) {
    // Block tile: 64 px wide x 4 rows. Grid = 8 x-chunks * 128 y-chunks * 8 b.
    int blk = blockIdx.x;
    int x0 = (blk & 7) << 6;            // x-chunk * 64
    int y0 = ((blk >> 3) & 127) << 2;   // y-chunk * 4
    int b  = blk >> 10;                 // batch

    int w = x0 + (threadIdx.x & 63);
    int h = y0 + (threadIdx.x >> 6);
    int hw = (h << 9) | w;

    const float* fl = flow + ((size_t)b << 19); // b * 2 * HWSZ
    float dx = __ldg(fl + hw);
    float dy = __ldg(fl + HWSZ + hw);

    float xf = (float)w + dx;
    float yf = (float)h + dy;
    float x0f = floorf(xf);
    float y0f = floorf(yf);
    float alpha = xf - x0f;   // unclamped fractional weights
    float beta  = yf - y0f;

    int ix0 = (int)x0f;
    int iy0 = (int)y0f;
    int xL = min(max(ix0,     0), WW - 1);
    int xR = min(max(ix0 + 1, 0), WW - 1);
    int yT = min(max(iy0,     0), HH - 1);
    int yB = min(max(iy0 + 1, 0), HH - 1);

    float wTR = alpha * (1.0f - beta);
    float wBL = (1.0f - alpha) * beta;
    float wBR = alpha * beta;
    float wTL = 1.0f - wTR - wBL - wBR;

    const float* base = in1 + ((size_t)b << 23);   // b * C * HWSZ
    const float* pTL = base + ((yT << 9) + xL);
    const float* pTR = base + ((yT << 9) + xR);
    const float* pBL = base + ((yB << 9) + xL);
    const float* pBR = base + ((yB << 9) + xR);
    float* op = out + ((size_t)b << 23) + hw;

    #pragma unroll 4
    for (int c = 0; c < CC; c++) {
        int off = c << 18;   // c * HWSZ
        float v = wTL * __ldg(pTL + off)
                + wTR * __ldg(pTR + off)
                + wBL * __ldg(pBL + off)
                + wBR * __ldg(pBR + off);
        op[off] = v;
    }
}

extern "C" void kernel_launch(void* const* d_in, const int* in_sizes, int n_in,
                              void* d_out, int out_size) {
    const float* input1 = (const float*)d_in[0];
    const float* input2 = (const float*)d_in[1];
    float* out = (float*)d_out;

    const int blocks = 8 * 128 * BB;   // 8192 tiles of 64x4
    resample2d_kernel<<<blocks, 256>>>(input1, input2, out);
}

// round 17
// speedup vs baseline: 1.0291x; 1.0090x over previous
#include <cuda_runtime.h>

// FlowNet2 Resample2d (kernel_size=1) bilinear warp — FINAL (converged).
// input1: [B, C, H, W] float, input2 (flow): [B, 2, H, W] float
//
// Converged after 16 measured rounds: 64x4 pixel tiles (256 threads, warps
// = 32-px half-rows, vertically adjacent rows co-resident per SM), one
// thread per pixel, scalar gathers, channel loop unroll-4, 32 regs,
// 8 blocks/SM (~93% occupancy). 124.6-129us ncu (noise band +/-3-4us,
// established by identical-code reruns), ~4.1 TB/s HBM, L1 ~85-88% busy.
//
// Performance model (HW-calibrated): L1 sector-return bound at ~14 L1
// cycles per warp-channel = 4 scattered gathers x ~3.4 unique-sector
// wavefronts + 1 coalesced store wavefront. Geometry audit: warp=32px x 1ch
// is the px-densest gather arrangement (8px x 4ch => ~40 sectors/unit,
// lane=channel => ~128; both strictly worse). Shuffle TR-recovery: only
// ~27% hit rate under N(0,1) flow. Sector bill is a warp-footprint
// invariant — load width and lane permutation cannot reduce it.
//
// Measured dead ends: LDG.64/LDG.128 gathers (165/253us — scattered wide
// loads pay the sector bill per 4B slice), smem staging (LDS conflicts +
// instr bloat, 395us), channel-lockstep barriers (174us), 32x8 / 64x2
// tiles (lose vertical reuse or L1 density), __stcg, unroll-8 (occupancy),
// dual channel streams (issue pressure), paired sequential tiles (temporal
// locality loss, 143us), smem carveout (neutral), L1::evict_last (way
// contention, 130us). tex2Dgather barred (requires CUDA array allocation).

#define BB 8
#define CC 32
#define HH 512
#define WW 512
#define HWSZ (HH * WW)   // 2^18

__global__ __launch_bounds__(256, 8)
void resample2d_kernel(const float* __restrict__ in1,
                       const float* __restrict__ flow,
                       float* __restrict__ out) {
    // Block tile: 64 px wide x 4 rows. Grid = 8 x-chunks * 128 y-chunks * 8 b.
    int blk = blockIdx.x;
    int x0 = (blk & 7) << 6;            // x-chunk * 64
    int y0 = ((blk >> 3) & 127) << 2;   // y-chunk * 4
    int b  = blk >> 10;                 // batch

    int w = x0 + (threadIdx.x & 63);
    int h = y0 + (threadIdx.x >> 6);
    int hw = (h << 9) | w;

    const float* fl = flow + ((size_t)b << 19); // b * 2 * HWSZ
    float dx = __ldg(fl + hw);
    float dy = __ldg(fl + HWSZ + hw);

    float xf = (float)w + dx;
    float yf = (float)h + dy;
    float x0f = floorf(xf);
    float y0f = floorf(yf);
    float alpha = xf - x0f;   // unclamped fractional weights
    float beta  = yf - y0f;

    int ix0 = (int)x0f;
    int iy0 = (int)y0f;
    int xL = min(max(ix0,     0), WW - 1);
    int xR = min(max(ix0 + 1, 0), WW - 1);
    int yT = min(max(iy0,     0), HH - 1);
    int yB = min(max(iy0 + 1, 0), HH - 1);

    float wTR = alpha * (1.0f - beta);
    float wBL = (1.0f - alpha) * beta;
    float wBR = alpha * beta;
    float wTL = 1.0f - wTR - wBL - wBR;

    const float* base = in1 + ((size_t)b << 23);   // b * C * HWSZ
    const float* pTL = base + ((yT << 9) + xL);
    const float* pTR = base + ((yT << 9) + xR);
    const float* pBL = base + ((yB << 9) + xL);
    const float* pBR = base + ((yB << 9) + xR);
    float* op = out + ((size_t)b << 23) + hw;

    #pragma unroll 4
    for (int c = 0; c < CC; c++) {
        int off = c << 18;   // c * HWSZ
        float v = wTL * __ldg(pTL + off)
                + wTR * __ldg(pTR + off)
                + wBL * __ldg(pBL + off)
                + wBR * __ldg(pBR + off);
        op[off] = v;
    }
}

extern "C" void kernel_launch(void* const* d_in, const int* in_sizes, int n_in,
                              void* d_out, int out_size) {
    const float* input1 = (const float*)d_in[0];
    const float* input2 = (const float*)d_in[1];
    float* out = (float*)d_out;

    const int blocks = 8 * 128 * BB;   // 8192 tiles of 64x4
    resample2d_kernel<<<blocks, 256>>>(input1, input2, out);
}